// round 4
// baseline (speedup 1.0000x reference)
#include <cuda_runtime.h>
#include <cstdint>

// Problem constants
#define Bc   4
#define Sc   2048
#define Ec   1024
#define Hc   16
#define Dc   64
#define WINc 512
#define E3c  3072
#define NTOK 8192   // B*S

// Scratch (device globals: allocation-free per harness rules)
__device__ float g_qkv[(size_t)NTOK * E3c];  // [tok, 3E]  (q | k | v)
__device__ float g_o[(size_t)NTOK * Ec];     // [tok, E] attention output

// ---------------------------------------------------------------------------
// helpers
// ---------------------------------------------------------------------------
__device__ __forceinline__ float cvt_tf32(float x) {
    unsigned u;
    asm("cvt.rna.tf32.f32 %0, %1;" : "=r"(u) : "f"(x));
    return __uint_as_float(u);
}

__device__ __forceinline__ void mma_tf32(float* c, const unsigned* a, const unsigned* b) {
    asm volatile(
        "mma.sync.aligned.m16n8k8.row.col.f32.tf32.tf32.f32 "
        "{%0,%1,%2,%3}, {%4,%5,%6,%7}, {%8,%9}, {%0,%1,%2,%3};"
        : "+f"(c[0]), "+f"(c[1]), "+f"(c[2]), "+f"(c[3])
        : "r"(a[0]), "r"(a[1]), "r"(a[2]), "r"(a[3]), "r"(b[0]), "r"(b[1]));
}

typedef unsigned long long u64;

__device__ __forceinline__ u64 pack2(float lo, float hi) {
    u64 r;
    asm("mov.b64 %0, {%1,%2};" : "=l"(r) : "f"(lo), "f"(hi));
    return r;
}
__device__ __forceinline__ void unpack2(u64 v, float& lo, float& hi) {
    asm("mov.b64 {%0,%1}, %2;" : "=f"(lo), "=f"(hi) : "l"(v));
}
__device__ __forceinline__ u64 ffma2(u64 a, u64 b, u64 c) {
    u64 d;
    asm("fma.rn.f32x2 %0, %1, %2, %3;" : "=l"(d) : "l"(a), "l"(b), "l"(c));
    return d;
}
__device__ __forceinline__ u64 fmul2(u64 a, u64 b) {
    u64 d;
    asm("mul.rn.f32x2 %0, %1, %2;" : "=l"(d) : "l"(a), "l"(b));
    return d;
}

// ---------------------------------------------------------------------------
// NT GEMM (tf32 tensor cores): C[M,N] = A[M,K] * B[N,K]^T, all row-major fp32.
// BM=BN=128, BK=32, 256 threads, 8 warps each computing 64x32.
// Double-buffered smem: ONE __syncthreads per K-tile; STS.128 staging stores.
// ---------------------------------------------------------------------------
#define LDT 36  // smem row stride (32 + 4): frag loads bank-conflict-free
#define TILE_F (128 * LDT)
#define GEMM_SMEM_BYTES (4 * TILE_F * 4)  // sA[2] + sB[2]

__global__ __launch_bounds__(256, 2)
void gemm_nt_tf32(const float* __restrict__ A, const float* __restrict__ Bm,
                  float* __restrict__ C, int M, int N, int K) {
    extern __shared__ float smem[];
    float* sAb = smem;               // [2][TILE_F]
    float* sBb = smem + 2 * TILE_F;  // [2][TILE_F]

    const int tid  = threadIdx.x;
    const int lane = tid & 31;
    const int warp = tid >> 5;
    const int wm   = (warp & 1) * 64;   // warp m-offset within block
    const int wn   = (warp >> 1) * 32;  // warp n-offset within block
    const int bm   = blockIdx.y;
    const int bn   = blockIdx.x;
    const int nk   = K >> 5;

    const int ldr = tid >> 3;   // 0..31 (+32*i)
    const int ldc = tid & 7;    // float4 column

    float c[4][4][4];
#pragma unroll
    for (int mi = 0; mi < 4; mi++)
#pragma unroll
        for (int ni = 0; ni < 4; ni++)
#pragma unroll
            for (int r = 0; r < 4; r++) c[mi][ni][r] = 0.0f;

    // prologue: stage tile 0 into registers
    float4 ra[4], rb[4];
#pragma unroll
    for (int i = 0; i < 4; i++) {
        int row = ldr + 32 * i;
        ra[i] = *(const float4*)(A + (size_t)(bm * 128 + row) * K + ldc * 4);
        rb[i] = *(const float4*)(Bm + (size_t)(bn * 128 + row) * K + ldc * 4);
    }

    for (int kb = 0; kb < nk; kb++) {
        float* dA = sAb + (kb & 1) * TILE_F;
        float* dB = sBb + (kb & 1) * TILE_F;

        // store staged tile (tf32-rounded, vectorized STS.128)
#pragma unroll
        for (int i = 0; i < 4; i++) {
            int row = ldr + 32 * i;
            float4 t;
            t.x = cvt_tf32(ra[i].x); t.y = cvt_tf32(ra[i].y);
            t.z = cvt_tf32(ra[i].z); t.w = cvt_tf32(ra[i].w);
            *(float4*)&dA[row * LDT + ldc * 4] = t;
            float4 u;
            u.x = cvt_tf32(rb[i].x); u.y = cvt_tf32(rb[i].y);
            u.z = cvt_tf32(rb[i].z); u.w = cvt_tf32(rb[i].w);
            *(float4*)&dB[row * LDT + ldc * 4] = u;
        }

        // stage next tile while this one is being consumed
        if (kb + 1 < nk) {
#pragma unroll
            for (int i = 0; i < 4; i++) {
                int row = ldr + 32 * i;
                ra[i] = *(const float4*)(A + (size_t)(bm * 128 + row) * K + (kb + 1) * 32 + ldc * 4);
                rb[i] = *(const float4*)(Bm + (size_t)(bn * 128 + row) * K + (kb + 1) * 32 + ldc * 4);
            }
        }
        __syncthreads();  // tile kb visible; buffer (kb+1)&1 free (read finished iter kb-1)

#pragma unroll
        for (int kk = 0; kk < 4; kk++) {
            const int k0 = kk * 8;
            unsigned afr[4][4], bfr[4][2];
#pragma unroll
            for (int mi = 0; mi < 4; mi++) {
                int r0 = wm + mi * 16 + (lane >> 2);
                int cc = k0 + (lane & 3);
                afr[mi][0] = __float_as_uint(dA[r0 * LDT + cc]);
                afr[mi][1] = __float_as_uint(dA[(r0 + 8) * LDT + cc]);
                afr[mi][2] = __float_as_uint(dA[r0 * LDT + cc + 4]);
                afr[mi][3] = __float_as_uint(dA[(r0 + 8) * LDT + cc + 4]);
            }
#pragma unroll
            for (int ni = 0; ni < 4; ni++) {
                int rn = wn + ni * 8 + (lane >> 2);
                int cc = k0 + (lane & 3);
                bfr[ni][0] = __float_as_uint(dB[rn * LDT + cc]);
                bfr[ni][1] = __float_as_uint(dB[rn * LDT + cc + 4]);
            }
#pragma unroll
            for (int mi = 0; mi < 4; mi++)
#pragma unroll
                for (int ni = 0; ni < 4; ni++) mma_tf32(c[mi][ni], afr[mi], bfr[ni]);
        }
        // no second sync: next iteration writes the OTHER buffer
    }

    // epilogue
#pragma unroll
    for (int mi = 0; mi < 4; mi++) {
        int row = bm * 128 + wm + mi * 16 + (lane >> 2);
#pragma unroll
        for (int ni = 0; ni < 4; ni++) {
            int col = bn * 128 + wn + ni * 8 + 2 * (lane & 3);
            C[(size_t)row * N + col]           = c[mi][ni][0];
            C[(size_t)row * N + col + 1]       = c[mi][ni][1];
            C[(size_t)(row + 8) * N + col]     = c[mi][ni][2];
            C[(size_t)(row + 8) * N + col + 1] = c[mi][ni][3];
        }
    }
}

// ---------------------------------------------------------------------------
// Sliding-window attention with ALiBi, flash-style, one thread = one query.
// Block = 128 queries for one (b, h). Q + accumulator packed as f32x2 pairs,
// K/V streamed through smem in 64-key chunks (broadcast LDS.128).
// Branch-free 8-key batches; log2-domain softmax (bare MUFU.EX2);
// rescale only when the running max actually increases (ALiBi makes the
// first unmasked batch dominate, so this is rare) — warp-uniform guard.
// scores(log2) = (q.k)*(0.125*log2e) + slope2*(q_idx-kv_idx), mask 0<=d<=512.
// ---------------------------------------------------------------------------
__global__ __launch_bounds__(128, 3)
void attn_kernel() {
    __shared__ float sm[8704];  // Q/out staging (128*68); K@0, V@4096 (stride 64)

    const int tid = threadIdx.x;
    const int qt  = blockIdx.x;
    const int h   = blockIdx.y;
    const int b   = blockIdx.z;
    const int qstart = qt * 128;

    // ---- stage Q tile (coalesced) then copy own row into packed regs ----
    const size_t base_q = (size_t)(b * Sc + qstart) * E3c + h * Dc;
#pragma unroll
    for (int i = 0; i < 16; i++) {
        int f = tid + i * 128;
        int ql = f >> 4, c4 = f & 15;
        *(float4*)&sm[ql * 68 + c4 * 4] =
            *(const float4*)(g_qkv + base_q + (size_t)ql * E3c + c4 * 4);
    }
    __syncthreads();

    u64 q2[32];
#pragma unroll
    for (int j = 0; j < 32; j++) q2[j] = *(const u64*)&sm[tid * 68 + 2 * j];
    __syncthreads();

    u64 acc2[32];
#pragma unroll
    for (int j = 0; j < 32; j++) acc2[j] = 0ull;
    float m = -1e29f, l = 0.0f;   // m, scores in log2 domain

    const int   qpos   = qstart + tid;
    const int   q0w    = qstart + (tid & ~31);  // warp's first query position
    const float LOG2E  = 1.4426950408889634f;
    const float sscale = 0.125f * LOG2E;
    const float slope2 = exp2f(-(float)(h + 1) * 0.5f) * LOG2E;

    int kb0 = qstart - WINc;
    if (kb0 < 0) kb0 = 0;

    for (int kb = kb0; kb < qstart + 128; kb += 64) {
        // load K and V chunks [64][64] (coalesced)
#pragma unroll
        for (int i = 0; i < 8; i++) {
            int f = tid + i * 128;
            int r = f >> 4, c4 = f & 15;
            size_t gb = (size_t)(b * Sc + kb + r) * E3c + h * Dc + c4 * 4;
            *(float4*)&sm[r * 64 + c4 * 4]        = *(const float4*)(g_qkv + gb + Ec);
            *(float4*)&sm[4096 + r * 64 + c4 * 4] = *(const float4*)(g_qkv + gb + 2 * Ec);
        }
        __syncthreads();

        // warp-uniform batch range (no intra-warp loop-bound divergence)
        int wjlo = q0w - WINc - kb;  if (wjlo < 0) wjlo = 0;
        int wjhi = q0w + 31 - kb;    if (wjhi > 63) wjhi = 63;

        for (int j0 = wjlo & ~7; j0 <= wjhi; j0 += 8) {
            // ---- scores for 8 keys: 2 ffma2 chains each (16 chains in flight) ----
            float s[8];
#pragma unroll
            for (int i = 0; i < 8; i++) {
                const ulonglong2* kp = (const ulonglong2*)&sm[(j0 + i) * 64];
                u64 c0 = 0ull, c1 = 0ull;
#pragma unroll
                for (int jj = 0; jj < 16; jj++) {
                    ulonglong2 ka = kp[jj];
                    c0 = ffma2(q2[2 * jj + 0], ka.x, c0);
                    c1 = ffma2(q2[2 * jj + 1], ka.y, c1);
                }
                float a0, a1, b0, b1;
                unpack2(c0, a0, a1); unpack2(c1, b0, b1);
                float dot = (a0 + b0) + (a1 + b1);
                int delta = qpos - (kb + j0 + i);
                float sv = dot * sscale + slope2 * (float)delta;
                s[i] = ((unsigned)delta <= (unsigned)WINc) ? sv : -1e30f;
            }

            // ---- online softmax (log2 domain), rescale only if max grows ----
            float m01 = fmaxf(s[0], s[1]), m23 = fmaxf(s[2], s[3]);
            float m45 = fmaxf(s[4], s[5]), m67 = fmaxf(s[6], s[7]);
            float bmax = fmaxf(fmaxf(m01, m23), fmaxf(m45, m67));

            if (__any_sync(0xffffffffu, bmax > m)) {
                float mnew = fmaxf(m, bmax);
                float corr = exp2f(m - mnew);
                m = mnew;
                l *= corr;
                u64 cc2 = pack2(corr, corr);
#pragma unroll
                for (int jj = 0; jj < 32; jj++) acc2[jj] = fmul2(acc2[jj], cc2);
            }

            float p[8];
#pragma unroll
            for (int i = 0; i < 8; i++) p[i] = exp2f(s[i] - m);
            float ps = ((p[0] + p[1]) + (p[2] + p[3])) + ((p[4] + p[5]) + (p[6] + p[7]));
            l += ps;

            // ---- PV accumulate: 8 keys ----
#pragma unroll
            for (int i = 0; i < 8; i++) {
                u64 p2 = pack2(p[i], p[i]);
                const ulonglong2* vp = (const ulonglong2*)&sm[4096 + (j0 + i) * 64];
#pragma unroll
                for (int jj = 0; jj < 16; jj++) {
                    ulonglong2 v01 = vp[jj];
                    acc2[2 * jj]     = ffma2(p2, v01.x, acc2[2 * jj]);
                    acc2[2 * jj + 1] = ffma2(p2, v01.y, acc2[2 * jj + 1]);
                }
            }
        }
        __syncthreads();
    }

    // ---- normalize, stage to smem, coalesced store to g_o [tok, E] ----
    float inv = 1.0f / l;
#pragma unroll
    for (int jj = 0; jj < 32; jj++) {
        float a0, a1;
        unpack2(acc2[jj], a0, a1);
        sm[tid * 68 + 2 * jj]     = a0 * inv;
        sm[tid * 68 + 2 * jj + 1] = a1 * inv;
    }
    __syncthreads();

    const size_t base_o = (size_t)(b * Sc + qstart) * Ec + h * Dc;
#pragma unroll
    for (int i = 0; i < 16; i++) {
        int f = tid + i * 128;
        int ql = f >> 4, c4 = f & 15;
        *(float4*)(g_o + base_o + (size_t)ql * Ec + c4 * 4) =
            *(const float4*)&sm[ql * 68 + c4 * 4];
    }
}

// ---------------------------------------------------------------------------
// launch
// ---------------------------------------------------------------------------
extern "C" void kernel_launch(void* const* d_in, const int* in_sizes, int n_in,
                              void* d_out, int out_size) {
    const float* x     = (const float*)d_in[0];  // [B,S,E]
    const float* w_in  = (const float*)d_in[1];  // [3E,E]
    const float* w_out = (const float*)d_in[2];  // [E,E]
    float* out = (float*)d_out;                  // [B,S,E]

    float *qkv_ptr, *o_ptr;
    cudaGetSymbolAddress((void**)&qkv_ptr, g_qkv);
    cudaGetSymbolAddress((void**)&o_ptr, g_o);

    cudaFuncSetAttribute(gemm_nt_tf32, cudaFuncAttributeMaxDynamicSharedMemorySize,
                         GEMM_SMEM_BYTES);

    // 1) qkv = x @ w_in^T   : [8192,3072]
    gemm_nt_tf32<<<dim3(E3c / 128, NTOK / 128), 256, GEMM_SMEM_BYTES>>>(x, w_in, qkv_ptr, NTOK, E3c, Ec);
    // 2) sliding-window attention -> g_o [8192,1024]
    attn_kernel<<<dim3(Sc / 128, Hc, Bc), 128>>>();
    // 3) out = o @ w_out^T  : [8192,1024]
    gemm_nt_tf32<<<dim3(Ec / 128, NTOK / 128), 256, GEMM_SMEM_BYTES>>>(o_ptr, w_out, out, NTOK, Ec, Ec);
}

// round 6
// speedup vs baseline: 1.4523x; 1.4523x over previous
#include <cuda_runtime.h>
#include <cuda_fp16.h>
#include <cstdint>

// Problem constants
#define Bc   4
#define Sc   2048
#define Ec   1024
#define Hc   16
#define Dc   64
#define WINc 512
#define E3c  3072
#define NTOK 8192   // B*S

// Scratch (device globals: allocation-free per harness rules)
__device__ float g_qkv[(size_t)NTOK * E3c];  // [tok, 3E]  (q | k | v)
__device__ float g_o[(size_t)NTOK * Ec];     // [tok, E] attention output

// ---------------------------------------------------------------------------
// helpers
// ---------------------------------------------------------------------------
typedef unsigned long long u64;

__device__ __forceinline__ u64 pack2(float lo, float hi) {
    u64 r;
    asm("mov.b64 %0, {%1,%2};" : "=l"(r) : "f"(lo), "f"(hi));
    return r;
}
__device__ __forceinline__ void unpack2(u64 v, float& lo, float& hi) {
    asm("mov.b64 {%0,%1}, %2;" : "=f"(lo), "=f"(hi) : "l"(v));
}
__device__ __forceinline__ u64 ffma2(u64 a, u64 b, u64 c) {
    u64 d;
    asm("fma.rn.f32x2 %0, %1, %2, %3;" : "=l"(d) : "l"(a), "l"(b), "l"(c));
    return d;
}
__device__ __forceinline__ u64 fmul2(u64 a, u64 b) {
    u64 d;
    asm("mul.rn.f32x2 %0, %1, %2;" : "=l"(d) : "l"(a), "l"(b));
    return d;
}
__device__ __forceinline__ float ex2(float x) {
    float y;
    asm("ex2.approx.f32 %0, %1;" : "=f"(y) : "f"(x));
    return y;
}

__device__ __forceinline__ void ldmatrix_x4(unsigned* r, unsigned addr) {
    asm volatile("ldmatrix.sync.aligned.m8n8.x4.shared.b16 {%0,%1,%2,%3}, [%4];"
                 : "=r"(r[0]), "=r"(r[1]), "=r"(r[2]), "=r"(r[3]) : "r"(addr));
}

__device__ __forceinline__ void mma_f16(float* c, const unsigned* a, const unsigned* b) {
    asm volatile(
        "mma.sync.aligned.m16n8k16.row.col.f32.f16.f16.f32 "
        "{%0,%1,%2,%3}, {%4,%5,%6,%7}, {%8,%9}, {%0,%1,%2,%3};"
        : "+f"(c[0]), "+f"(c[1]), "+f"(c[2]), "+f"(c[3])
        : "r"(a[0]), "r"(a[1]), "r"(a[2]), "r"(a[3]), "r"(b[0]), "r"(b[1]));
}

__device__ __forceinline__ void cp16(unsigned saddr, const void* gptr) {
    asm volatile("cp.async.ca.shared.global [%0], [%1], 16;" :: "r"(saddr), "l"(gptr));
}
#define CP_COMMIT() asm volatile("cp.async.commit_group;" ::: "memory")
#define CP_WAIT0()  asm volatile("cp.async.wait_group 0;" ::: "memory")

// ---------------------------------------------------------------------------
// NT GEMM, fp16 tensor cores, fp32 accumulate:
//   C[M,N] = A[M,K] * B[N,K]^T   (A,B,C fp32 in gmem; staged fp16 in smem)
// BM=BN=128, BK=32, 256 threads, 8 warps each computing 64x32.
// Double-buffered smem, one __syncthreads per K-tile, ldmatrix fragment loads.
// fp16 mantissa == tf32 mantissa (11 bit) -> same accuracy as tf32 path.
// ---------------------------------------------------------------------------
#define LDH 40                 // halfs per smem row (80B stride: ldmatrix conflict-free)
#define TILE_H (128 * LDH)     // halfs per tile buffer

__global__ __launch_bounds__(256, 2)
void gemm_nt_f16(const float* __restrict__ A, const float* __restrict__ Bm,
                 float* __restrict__ C, int M, int N, int K) {
    __shared__ __half sh[4 * TILE_H];   // A[2] | B[2]  (40 KB)
    __half* sA = sh;
    __half* sB = sh + 2 * TILE_H;

    const int tid  = threadIdx.x;
    const int lane = tid & 31;
    const int warp = tid >> 5;
    const int wm   = (warp & 1) * 64;   // warp m-offset within block
    const int wn   = (warp >> 1) * 32;  // warp n-offset within block
    const int bm   = blockIdx.y;
    const int bn   = blockIdx.x;
    const int nk   = K >> 5;

    const int ldr = tid >> 3;   // staging row 0..31 (+32*i)
    const int ldc = tid & 7;    // staging float4 column

    const unsigned sA_u = (unsigned)__cvta_generic_to_shared(sA);
    const unsigned sB_u = (unsigned)__cvta_generic_to_shared(sB);

    // per-lane ldmatrix address components (halfs)
    const int a_row = (lane & 15);                      // + wm + mi*16
    const int a_kh  = (lane & 16) >> 1;                 // +8 halfs for upper matrices
    const int b_row = (lane & 7) + ((lane & 16) >> 1);  // + wn + nip*16
    const int b_kh  = (lane & 8);

    float c[4][4][4];
#pragma unroll
    for (int mi = 0; mi < 4; mi++)
#pragma unroll
        for (int ni = 0; ni < 4; ni++)
#pragma unroll
            for (int r = 0; r < 4; r++) c[mi][ni][r] = 0.0f;

    // prologue: stage tile 0 into registers
    float4 ra[4], rb[4];
#pragma unroll
    for (int i = 0; i < 4; i++) {
        int row = ldr + 32 * i;
        ra[i] = *(const float4*)(A + (size_t)(bm * 128 + row) * K + ldc * 4);
        rb[i] = *(const float4*)(Bm + (size_t)(bn * 128 + row) * K + ldc * 4);
    }

    for (int kb = 0; kb < nk; kb++) {
        const int boff = (kb & 1) * TILE_H;
        __half* dA = sA + boff;
        __half* dB = sB + boff;

        // store staged tile as fp16 (STS.64)
#pragma unroll
        for (int i = 0; i < 4; i++) {
            int row = ldr + 32 * i;
            __half2* pa = (__half2*)&dA[row * LDH + ldc * 4];
            pa[0] = __floats2half2_rn(ra[i].x, ra[i].y);
            pa[1] = __floats2half2_rn(ra[i].z, ra[i].w);
            __half2* pb = (__half2*)&dB[row * LDH + ldc * 4];
            pb[0] = __floats2half2_rn(rb[i].x, rb[i].y);
            pb[1] = __floats2half2_rn(rb[i].z, rb[i].w);
        }

        // stage next tile while this one is being consumed
        if (kb + 1 < nk) {
#pragma unroll
            for (int i = 0; i < 4; i++) {
                int row = ldr + 32 * i;
                ra[i] = *(const float4*)(A + (size_t)(bm * 128 + row) * K + (kb + 1) * 32 + ldc * 4);
                rb[i] = *(const float4*)(Bm + (size_t)(bn * 128 + row) * K + (kb + 1) * 32 + ldc * 4);
            }
        }
        __syncthreads();  // tile kb visible; other buffer free

#pragma unroll
        for (int kk = 0; kk < 2; kk++) {      // two k16 steps per 32-tile
            unsigned afr[4][4], bfr[2][4];
#pragma unroll
            for (int mi = 0; mi < 4; mi++) {
                unsigned addr = sA_u + 2u * (unsigned)(boff +
                    (wm + mi * 16 + a_row) * LDH + kk * 16 + a_kh);
                ldmatrix_x4(afr[mi], addr);
            }
#pragma unroll
            for (int nip = 0; nip < 2; nip++) {
                unsigned addr = sB_u + 2u * (unsigned)(boff +
                    (wn + nip * 16 + b_row) * LDH + kk * 16 + b_kh);
                ldmatrix_x4(bfr[nip], addr);   // regs: b0(n..n+7) b1(n..n+7) b0(n+8..) b1(n+8..)
            }
#pragma unroll
            for (int mi = 0; mi < 4; mi++)
#pragma unroll
                for (int ni = 0; ni < 4; ni++)
                    mma_f16(c[mi][ni], afr[mi], &bfr[ni >> 1][(ni & 1) * 2]);
        }
        // no second sync: next iteration writes the OTHER buffer
    }

    // epilogue (same c-frag mapping as m16n8k8)
#pragma unroll
    for (int mi = 0; mi < 4; mi++) {
        int row = bm * 128 + wm + mi * 16 + (lane >> 2);
#pragma unroll
        for (int ni = 0; ni < 4; ni++) {
            int col = bn * 128 + wn + ni * 8 + 2 * (lane & 3);
            C[(size_t)row * N + col]           = c[mi][ni][0];
            C[(size_t)row * N + col + 1]       = c[mi][ni][1];
            C[(size_t)(row + 8) * N + col]     = c[mi][ni][2];
            C[(size_t)(row + 8) * N + col + 1] = c[mi][ni][3];
        }
    }
}

// ---------------------------------------------------------------------------
// Sliding-window attention with ALiBi, flash-style, one thread = one query.
// Block = 128 queries for one (b, h). Q + accumulator packed as f32x2 pairs.
// K/V streamed through DOUBLE-BUFFERED smem in 64-key chunks via cp.async:
// chunk i+1's loads are issued before computing chunk i, so LDG latency is
// fully overlapped (no register staging, no scoreboard block at issue).
// Branch-free 8-key batches; log2-domain softmax (bare MUFU.EX2);
// rescale only when the running max actually increases (warp-uniform guard).
// scores(log2) = (q.k)*(0.125*log2e) + slope2*(q_idx-kv_idx), mask 0<=d<=512.
// smem layout (floats): buf p at p*8192: K[64*64] then V[64*64]. 64 KB total.
// Q/out staging (128*68=8704 floats) overlays the buffers outside the loop.
// ---------------------------------------------------------------------------
#define ATTN_SMEM_BYTES (16384 * 4)

__global__ __launch_bounds__(128, 2)
void attn_kernel() {
    extern __shared__ float sm[];

    const int tid = threadIdx.x;
    const int qt  = blockIdx.x;
    const int h   = blockIdx.y;
    const int b   = blockIdx.z;
    const int qstart = qt * 128;

    // ---- stage Q tile (coalesced) then copy own row into packed regs ----
    const size_t base_q = (size_t)(b * Sc + qstart) * E3c + h * Dc;
#pragma unroll
    for (int i = 0; i < 16; i++) {
        int f = tid + i * 128;
        int ql = f >> 4, c4 = f & 15;
        *(float4*)&sm[ql * 68 + c4 * 4] =
            *(const float4*)(g_qkv + base_q + (size_t)ql * E3c + c4 * 4);
    }
    __syncthreads();

    u64 q2[32];
#pragma unroll
    for (int j = 0; j < 32; j++) q2[j] = *(const u64*)&sm[tid * 68 + 2 * j];
    __syncthreads();   // done reading Q staging; buffers may be written

    u64 acc2[32];
#pragma unroll
    for (int j = 0; j < 32; j++) acc2[j] = 0ull;
    float m = -1e29f, l = 0.0f;   // m, scores in log2 domain

    const int   qpos   = qstart + tid;
    const int   q0w    = qstart + (tid & ~31);  // warp's first query position
    const float LOG2E  = 1.4426950408889634f;
    const float sscale = 0.125f * LOG2E;
    const float slope2 = exp2f(-(float)(h + 1) * 0.5f) * LOG2E;

    int kb0 = qstart - WINc;
    if (kb0 < 0) kb0 = 0;
    const int nch = (qstart + 128 - kb0) >> 6;   // 2..10 chunks of 64 keys

    const unsigned sm_u = (unsigned)__cvta_generic_to_shared(sm);
    const int ldrr = tid >> 4;   // cp.async row 0..7 (+8*i)
    const int ldcc = tid & 15;   // 16B column

    // prologue: async-load chunk 0 into buffer 0
    {
        const int kb = kb0;
#pragma unroll
        for (int i = 0; i < 8; i++) {
            int r = ldrr + 8 * i;
            size_t gb = (size_t)(b * Sc + kb + r) * E3c + h * Dc + ldcc * 4;
            unsigned so = (unsigned)(r * 64 + ldcc * 4) * 4u;
            cp16(sm_u + so,          g_qkv + gb + Ec);       // K
            cp16(sm_u + 16384 + so,  g_qkv + gb + 2 * Ec);   // V
        }
        CP_COMMIT();
    }

    for (int ci = 0; ci < nch; ci++) {
        CP_WAIT0();
        __syncthreads();   // chunk ci visible to all; buffer ci^1 free

        // prefetch chunk ci+1 into the other buffer (async, overlaps compute)
        if (ci + 1 < nch) {
            const int kbn = kb0 + (ci + 1) * 64;
            const unsigned bo = ((ci + 1) & 1) * 32768u;  // bytes: 8192 floats
#pragma unroll
            for (int i = 0; i < 8; i++) {
                int r = ldrr + 8 * i;
                size_t gb = (size_t)(b * Sc + kbn + r) * E3c + h * Dc + ldcc * 4;
                unsigned so = bo + (unsigned)(r * 64 + ldcc * 4) * 4u;
                cp16(sm_u + so,         g_qkv + gb + Ec);
                cp16(sm_u + 16384 + so, g_qkv + gb + 2 * Ec);
            }
            CP_COMMIT();
        }

        const int kb = kb0 + ci * 64;
        const float* Kb = sm + (ci & 1) * 8192;
        const float* Vb = Kb + 4096;

        // warp-uniform batch range (no intra-warp loop-bound divergence)
        int wjlo = q0w - WINc - kb;  if (wjlo < 0) wjlo = 0;
        int wjhi = q0w + 31 - kb;    if (wjhi > 63) wjhi = 63;

        for (int j0 = wjlo & ~7; j0 <= wjhi; j0 += 8) {
            // ---- scores for 8 keys: 2 ffma2 chains each (16 chains in flight) ----
            float s[8];
#pragma unroll
            for (int i = 0; i < 8; i++) {
                const ulonglong2* kp = (const ulonglong2*)&Kb[(j0 + i) * 64];
                u64 c0 = 0ull, c1 = 0ull;
#pragma unroll
                for (int jj = 0; jj < 16; jj++) {
                    ulonglong2 ka = kp[jj];
                    c0 = ffma2(q2[2 * jj + 0], ka.x, c0);
                    c1 = ffma2(q2[2 * jj + 1], ka.y, c1);
                }
                float a0, a1, b0, b1;
                unpack2(c0, a0, a1); unpack2(c1, b0, b1);
                float dot = (a0 + b0) + (a1 + b1);
                int delta = qpos - (kb + j0 + i);
                float sv = dot * sscale + slope2 * (float)delta;
                s[i] = ((unsigned)delta <= (unsigned)WINc) ? sv : -1e30f;
            }

            // ---- online softmax (log2 domain), rescale only if max grows ----
            float m01 = fmaxf(s[0], s[1]), m23 = fmaxf(s[2], s[3]);
            float m45 = fmaxf(s[4], s[5]), m67 = fmaxf(s[6], s[7]);
            float bmax = fmaxf(fmaxf(m01, m23), fmaxf(m45, m67));

            if (__any_sync(0xffffffffu, bmax > m)) {
                float mnew = fmaxf(m, bmax);
                float corr = ex2(m - mnew);
                m = mnew;
                l *= corr;
                u64 cc2 = pack2(corr, corr);
#pragma unroll
                for (int jj = 0; jj < 32; jj++) acc2[jj] = fmul2(acc2[jj], cc2);
            }

            float p[8];
#pragma unroll
            for (int i = 0; i < 8; i++) p[i] = ex2(s[i] - m);
            float ps = ((p[0] + p[1]) + (p[2] + p[3])) + ((p[4] + p[5]) + (p[6] + p[7]));
            l += ps;

            // ---- PV accumulate: 8 keys ----
#pragma unroll
            for (int i = 0; i < 8; i++) {
                u64 p2 = pack2(p[i], p[i]);
                const ulonglong2* vp = (const ulonglong2*)&Vb[(j0 + i) * 64];
#pragma unroll
                for (int jj = 0; jj < 16; jj++) {
                    ulonglong2 v01 = vp[jj];
                    acc2[2 * jj]     = ffma2(p2, v01.x, acc2[2 * jj]);
                    acc2[2 * jj + 1] = ffma2(p2, v01.y, acc2[2 * jj + 1]);
                }
            }
        }
    }
    __syncthreads();   // all compute done before reusing smem for output staging

    // ---- normalize, stage to smem, coalesced store to g_o [tok, E] ----
    float inv = 1.0f / l;
#pragma unroll
    for (int jj = 0; jj < 32; jj++) {
        float a0, a1;
        unpack2(acc2[jj], a0, a1);
        sm[tid * 68 + 2 * jj]     = a0 * inv;
        sm[tid * 68 + 2 * jj + 1] = a1 * inv;
    }
    __syncthreads();

    const size_t base_o = (size_t)(b * Sc + qstart) * Ec + h * Dc;
#pragma unroll
    for (int i = 0; i < 16; i++) {
        int f = tid + i * 128;
        int ql = f >> 4, c4 = f & 15;
        *(float4*)(g_o + base_o + (size_t)ql * Ec + c4 * 4) =
            *(const float4*)&sm[ql * 68 + c4 * 4];
    }
}

// ---------------------------------------------------------------------------
// launch
// ---------------------------------------------------------------------------
extern "C" void kernel_launch(void* const* d_in, const int* in_sizes, int n_in,
                              void* d_out, int out_size) {
    const float* x     = (const float*)d_in[0];  // [B,S,E]
    const float* w_in  = (const float*)d_in[1];  // [3E,E]
    const float* w_out = (const float*)d_in[2];  // [E,E]
    float* out = (float*)d_out;                  // [B,S,E]

    float *qkv_ptr, *o_ptr;
    cudaGetSymbolAddress((void**)&qkv_ptr, g_qkv);
    cudaGetSymbolAddress((void**)&o_ptr, g_o);

    cudaFuncSetAttribute(attn_kernel, cudaFuncAttributeMaxDynamicSharedMemorySize,
                         ATTN_SMEM_BYTES);

    // 1) qkv = x @ w_in^T   : [8192,3072]
    gemm_nt_f16<<<dim3(E3c / 128, NTOK / 128), 256>>>(x, w_in, qkv_ptr, NTOK, E3c, Ec);
    // 2) sliding-window attention -> g_o [8192,1024]
    attn_kernel<<<dim3(Sc / 128, Hc, Bc), 128, ATTN_SMEM_BYTES>>>();
    // 3) out = o @ w_out^T  : [8192,1024]
    gemm_nt_f16<<<dim3(Ec / 128, NTOK / 128), 256>>>(o_ptr, w_out, out, NTOK, Ec, Ec);
}